// round 5
// baseline (speedup 1.0000x reference)
#include <cuda_runtime.h>
#include <math_constants.h>

#define BB 32
#define CC 1024
#define HW 784
#define NF4 196          // HW/4
#define REDU 64
#define TD 768
#define AD 256
#define NCH 32           // c-chunks for scores pass (32 channels each)

// ---- scratch (device globals; no allocation allowed) ----
__device__ float d_avg[BB*CC];
__device__ float d_maxv[BB*CC];
__device__ float d_chattn[BB*CC];
__device__ float d_g[BB*CC];      // qk*chattn/16
__device__ float d_h[BB*CC];      // u*chattn
__device__ float d_q[BB*AD];
__device__ float d_u[CC];
__device__ float d_pS[BB*NCH*HW]; // score partials
__device__ float d_pY[BB*NCH*HW]; // y partials
__device__ float d_s[BB];

__device__ __forceinline__ float warp_sum(float v){
  #pragma unroll
  for (int o=16;o;o>>=1) v += __shfl_xor_sync(0xffffffffu, v, o);
  return v;
}
__device__ __forceinline__ float warp_max(float v){
  #pragma unroll
  for (int o=16;o;o>>=1) v = fmaxf(v, __shfl_xor_sync(0xffffffffu, v, o));
  return v;
}

// ---------------------------------------------------------------------------
// Kernel A: fused front. blocks [0,4096): k1 mean/max sweep (warp per row).
//           blocks [4096,4100): u = wo@wv.  blocks [4100,4356): q = tf@wq^T.
// ---------------------------------------------------------------------------
__global__ void kA(const float* __restrict__ x,
                   const float* __restrict__ wv, const float* __restrict__ wo,
                   const float* __restrict__ tf, const float* __restrict__ wq){
  __shared__ float sh[TD];
  int bid = blockIdx.x, tid = threadIdx.x;
  if (bid < 4096){
    int warp = tid>>5, lane = tid&31;
    int row = bid*8 + warp;
    const float4* xr = (const float4*)(x + (size_t)row*HW);
    // fully batched loads: 6 unconditional + 1 predicated (196 float4 per row)
    float4 v0 = xr[lane      ];
    float4 v1 = xr[lane +  32];
    float4 v2 = xr[lane +  64];
    float4 v3 = xr[lane +  96];
    float4 v4 = xr[lane + 128];
    float4 v5 = xr[lane + 160];
    bool t = lane < 4;
    float4 v6 = t ? xr[lane + 192] : make_float4(0.f,0.f,0.f,0.f);
    float s = ((v0.x+v0.y)+(v0.z+v0.w)) + ((v1.x+v1.y)+(v1.z+v1.w))
            + ((v2.x+v2.y)+(v2.z+v2.w)) + ((v3.x+v3.y)+(v3.z+v3.w))
            + ((v4.x+v4.y)+(v4.z+v4.w)) + ((v5.x+v5.y)+(v5.z+v5.w))
            + ((v6.x+v6.y)+(v6.z+v6.w));
    float m = fmaxf(fmaxf(fmaxf(v0.x,v0.y),fmaxf(v0.z,v0.w)),
              fmaxf(fmaxf(fmaxf(v1.x,v1.y),fmaxf(v1.z,v1.w)),
              fmaxf(fmaxf(fmaxf(v2.x,v2.y),fmaxf(v2.z,v2.w)),
              fmaxf(fmaxf(fmaxf(v3.x,v3.y),fmaxf(v3.z,v3.w)),
              fmaxf(fmaxf(fmaxf(v4.x,v4.y),fmaxf(v4.z,v4.w)),
                    fmaxf(fmaxf(v5.x,v5.y),fmaxf(v5.z,v5.w)))))));
    if (t) m = fmaxf(m, fmaxf(fmaxf(v6.x,v6.y),fmaxf(v6.z,v6.w)));
    s = warp_sum(s); m = warp_max(m);
    if ((tid&31)==0){ d_avg[row] = s*(1.f/(float)HW); d_maxv[row] = m; }
  } else if (bid < 4100){
    // u[c] = sum_a wo[a]*wv[a,c]
    if (tid < AD) sh[tid] = wo[tid];
    __syncthreads();
    int c = (bid-4096)*256 + tid;
    float acc = 0.f;
    #pragma unroll 8
    for (int a=0;a<AD;a++) acc += sh[a]*wv[a*CC + c];
    d_u[c] = acc;
  } else {
    // q[b,a] = dot(tf[b,:], wq[a,:]); 256 blocks = (8 achunk x 32 b)
    int qb = bid - 4100;
    int chunk = qb & 7, b = qb >> 3;
    int warp = tid>>5, lane = tid&31;
    for (int i=tid;i<TD;i+=256) sh[i] = tf[b*TD+i];
    __syncthreads();
    int a0 = chunk*32 + warp*4;
    const float* w0 = wq + (a0+0)*TD;
    const float* w1 = wq + (a0+1)*TD;
    const float* w2 = wq + (a0+2)*TD;
    const float* w3 = wq + (a0+3)*TD;
    float acc0=0.f,acc1=0.f,acc2=0.f,acc3=0.f;
    #pragma unroll 4
    for (int i=lane;i<TD;i+=32){
      float tt = sh[i];
      acc0 += w0[i]*tt; acc1 += w1[i]*tt; acc2 += w2[i]*tt; acc3 += w3[i]*tt;
    }
    acc0=warp_sum(acc0); acc1=warp_sum(acc1); acc2=warp_sum(acc2); acc3=warp_sum(acc3);
    if (lane==0){
      d_q[b*AD+a0+0]=acc0; d_q[b*AD+a0+1]=acc1;
      d_q[b*AD+a0+2]=acc2; d_q[b*AD+a0+3]=acc3;
    }
  }
}

// ---------------------------------------------------------------------------
// Kernel B: per-b (512 thr): hidden MLP -> ch_attn; qk = q@wk inline -> g, h.
// ---------------------------------------------------------------------------
__global__ void kB(const float* __restrict__ w1, const float* __restrict__ w2,
                   const float* __restrict__ wk){
  cudaGridDependencySynchronize();
  int b = blockIdx.x, tid = threadIdx.x, warp = tid>>5, lane = tid&31;
  __shared__ float s_avg[CC], s_max[CC], s_hs[REDU], s_q[AD];
  #pragma unroll
  for (int j=0;j<2;j++){ int c=tid+512*j; s_avg[c]=d_avg[b*CC+c]; s_max[c]=d_maxv[b*CC+c]; }
  if (tid < AD) s_q[tid] = d_q[b*AD+tid];
  __syncthreads();
  // 16 warps x 4 rows, 2 rows at a time with ILP
  #pragma unroll
  for (int rr=0; rr<2; rr++){
    int r0 = warp*4 + rr*2;
    const float* wr0 = w1 + (size_t)r0*CC;
    const float* wr1 = wr0 + CC;
    float a0=0.f,m0=0.f,a1=0.f,m1=0.f;
    #pragma unroll 4
    for (int i=lane;i<CC;i+=32){
      float va=s_avg[i], vm=s_max[i];
      float u0=wr0[i], u1=wr1[i];
      a0+=u0*va; m0+=u0*vm; a1+=u1*va; m1+=u1*vm;
    }
    a0=warp_sum(a0); m0=warp_sum(m0); a1=warp_sum(a1); m1=warp_sum(m1);
    if (lane==0){
      s_hs[r0  ] = fmaxf(a0,0.f)+fmaxf(m0,0.f);
      s_hs[r0+1] = fmaxf(a1,0.f)+fmaxf(m1,0.f);
    }
  }
  __syncthreads();
  #pragma unroll
  for (int j=0;j<2;j++){
    int c = tid + 512*j;
    const float4* w2v = (const float4*)(w2 + (size_t)c*REDU);
    float acc = 0.f;
    #pragma unroll
    for (int r4=0;r4<REDU/4;r4++){
      float4 wv4 = w2v[r4];
      acc += wv4.x*s_hs[r4*4+0] + wv4.y*s_hs[r4*4+1]
           + wv4.z*s_hs[r4*4+2] + wv4.w*s_hs[r4*4+3];
    }
    float ch = 1.f/(1.f+__expf(-acc));
    float qk = 0.f;
    #pragma unroll 8
    for (int a=0;a<AD;a++) qk += s_q[a]*wk[a*CC + c];
    d_chattn[b*CC+c] = ch;
    d_g[b*CC+c] = qk * ch * 0.0625f;   // /sqrt(256)
    d_h[b*CC+c] = d_u[c] * ch;
  }
}

// ---------------------------------------------------------------------------
// Kernel C: dual channel-contraction, float4. grid (32, 32), 224 thr.
// ---------------------------------------------------------------------------
__global__ void kC(const float* __restrict__ x){
  cudaGridDependencySynchronize();
  int chunk = blockIdx.x, b = blockIdx.y, tid = threadIdx.x;
  __shared__ float sg[32], shh[32];
  if (tid<32){
    sg[tid]  = d_g[b*CC + chunk*32 + tid];
    shh[tid] = d_h[b*CC + chunk*32 + tid];
  }
  __syncthreads();
  if (tid >= NF4) return;
  const float4* xb4 = (const float4*)(x + ((size_t)b*CC + chunk*32)*HW);
  float4 aS = make_float4(0.f,0.f,0.f,0.f);
  float4 aY = make_float4(0.f,0.f,0.f,0.f);
  #pragma unroll 8
  for (int c=0;c<32;c++){
    float4 v = xb4[c*NF4 + tid];
    float gc = sg[c], hc = shh[c];
    aS.x += gc*v.x; aS.y += gc*v.y; aS.z += gc*v.z; aS.w += gc*v.w;
    aY.x += hc*v.x; aY.y += hc*v.y; aY.z += hc*v.z; aY.w += hc*v.w;
  }
  ((float4*)(d_pS + ((size_t)b*NCH + chunk)*HW))[tid] = aS;
  ((float4*)(d_pY + ((size_t)b*NCH + chunk)*HW))[tid] = aY;
}

// ---------------------------------------------------------------------------
// Kernel D: reduce partials, softmax, s[b]=sigmoid(sum e*y/sum e), out2.
// ---------------------------------------------------------------------------
__global__ void kD(float* __restrict__ out2){
  cudaGridDependencySynchronize();
  int b=blockIdx.x, tid=threadIdx.x, warp=tid>>5, lane=tid&31;
  __shared__ float redA[32], redB[32], bcast[1];
  __shared__ float s_sv;
  bool act = tid < HW;
  float sc = 0.f, y = 0.f;
  if (act){
    #pragma unroll 8
    for (int k=0;k<NCH;k++){
      size_t off = ((size_t)b*NCH+k)*HW + tid;
      sc += d_pS[off];
      y  += d_pY[off];
    }
  }
  float m = act ? sc : -CUDART_INF_F;
  m = warp_max(m);
  if (lane==0) redA[warp]=m;
  __syncthreads();
  if (tid==0){ float mm=redA[0]; for(int i=1;i<25;i++) mm=fmaxf(mm,redA[i]); bcast[0]=mm; }
  __syncthreads();
  float mm = bcast[0];
  float e = act ? __expf(sc-mm) : 0.f;
  float se  = warp_sum(e);
  float sey = warp_sum(e*y);
  __syncthreads();
  if (lane==0){ redA[warp]=se; redB[warp]=sey; }
  __syncthreads();
  if (tid==0){
    float te=0.f, tey=0.f;
    for(int i=0;i<25;i++){ te+=redA[i]; tey+=redB[i]; }
    float sv = 1.f/(1.f+__expf(-tey/te));
    d_s[b]=sv; s_sv=sv;
  }
  __syncthreads();
  if (out2 && act) out2[b*HW+tid] = s_sv;
}

// ---------------------------------------------------------------------------
// Kernel E: out[b,c,:] = x[b,c,:] * ch_attn[b,c] * s[b]. Warp per row.
// ---------------------------------------------------------------------------
__global__ void kE(const float* __restrict__ x, float* __restrict__ out){
  cudaGridDependencySynchronize();
  int warp=threadIdx.x>>5, lane=threadIdx.x&31;
  int row=blockIdx.x*8+warp;
  float scale = d_chattn[row]*d_s[row>>10];
  const float4* xr=(const float4*)(x+(size_t)row*HW);
  float4* orow=(float4*)(out+(size_t)row*HW);
  float4 v0 = xr[lane      ];
  float4 v1 = xr[lane +  32];
  float4 v2 = xr[lane +  64];
  float4 v3 = xr[lane +  96];
  float4 v4 = xr[lane + 128];
  float4 v5 = xr[lane + 160];
  bool t = lane < 4;
  float4 v6 = t ? xr[lane + 192] : make_float4(0.f,0.f,0.f,0.f);
  v0.x*=scale; v0.y*=scale; v0.z*=scale; v0.w*=scale;
  v1.x*=scale; v1.y*=scale; v1.z*=scale; v1.w*=scale;
  v2.x*=scale; v2.y*=scale; v2.z*=scale; v2.w*=scale;
  v3.x*=scale; v3.y*=scale; v3.z*=scale; v3.w*=scale;
  v4.x*=scale; v4.y*=scale; v4.z*=scale; v4.w*=scale;
  v5.x*=scale; v5.y*=scale; v5.z*=scale; v5.w*=scale;
  v6.x*=scale; v6.y*=scale; v6.z*=scale; v6.w*=scale;
  orow[lane      ] = v0;
  orow[lane +  32] = v1;
  orow[lane +  64] = v2;
  orow[lane +  96] = v3;
  orow[lane + 128] = v4;
  orow[lane + 160] = v5;
  if (t) orow[lane + 192] = v6;
}

// ---- PDL launch helper -----------------------------------------------------
template <typename K, typename... Args>
static void launch_pdl(K kern, dim3 grid, dim3 block, Args... args){
  cudaLaunchConfig_t cfg = {};
  cfg.gridDim = grid; cfg.blockDim = block; cfg.stream = 0;
  cudaLaunchAttribute attr[1];
  attr[0].id = cudaLaunchAttributeProgrammaticStreamSerialization;
  attr[0].val.programmaticStreamSerializationAllowed = 1;
  cfg.attrs = attr; cfg.numAttrs = 1;
  cudaLaunchKernelEx(&cfg, kern, args...);
}

extern "C" void kernel_launch(void* const* d_in, const int* in_sizes, int n_in,
                              void* d_out, int out_size){
  const float* x  = (const float*)d_in[0];
  const float* tf = (const float*)d_in[1];
  const float* w1 = (const float*)d_in[2];
  const float* w2 = (const float*)d_in[3];
  const float* wq = (const float*)d_in[4];
  const float* wk = (const float*)d_in[5];
  const float* wv = (const float*)d_in[6];
  const float* wo = (const float*)d_in[7];
  float* out = (float*)d_out;
  long long main_elems = (long long)BB*CC*HW;
  float* out2 = ((long long)out_size >= main_elems + (long long)BB*HW)
                  ? out + main_elems : nullptr;

  kA<<<4356, 256>>>(x, wv, wo, tf, wq);
  launch_pdl(kB, dim3(BB), dim3(512), w1, w2, wk);
  launch_pdl(kC, dim3(NCH, BB), dim3(224), x);
  launch_pdl(kD, dim3(BB), dim3(800), out2);
  launch_pdl(kE, dim3(4096), dim3(256), x, out);
}